// round 1
// baseline (speedup 1.0000x reference)
#include <cuda_runtime.h>

// Problem dims (fixed for this problem instance)
#define Bb   2
#define Ss   2048
#define Dd   1024
#define Hh   16
#define KVh  4
#define QKBd 16
#define VBd  32
#define MROWS (Bb*Ss)          // 4096
#define HVB   (Hh*VBd)         // 512

// ---------------- scratch (static device arrays; no allocation) -------------
__device__ __align__(16) float g_pq[Bb*Hh*Ss*QKBd];    // [(b*H+h)*S+s][16]
__device__ __align__(16) float g_pk[Bb*KVh*Ss*QKBd];   // [(b*KV+kv)*S+t][16]
__device__ __align__(16) float g_sk[Bb*KVh*Ss];        // row sums of pk
__device__ __align__(16) float g_pv[Bb*KVh*Ss*VBd];    // [(b*KV+kv)*S+t][32]
__device__ __align__(16) float g_vh[Bb*Ss*HVB];        // [b*S+s][h*32+j]
__device__ __align__(16) float g_bias[Dd];             // e0 @ Wo

// ---------------- Kernel 1: QKV projection GEMM + sigmoid --------------------
// C = sigmoid(A @ W); A = hidden [4096,1024]; W [1024,N]; scattered epilogue.
__global__ __launch_bounds__(256) void proj_kernel(
    const float* __restrict__ A, const float* __restrict__ W, int N, int mode)
{
    __shared__ float As[16][68];
    __shared__ float Bs[16][68];
    const int m0 = blockIdx.x * 64;
    const int n0 = blockIdx.y * 64;
    const int tid = threadIdx.x;
    const int tm = tid >> 4;       // 0..15
    const int tn = tid & 15;       // 0..15
    const int lrow = tid >> 2;     // 0..63 (A fill)
    const int lkp  = tid & 3;
    const int brow = tid >> 4;     // 0..15 (B fill)
    const int bnp  = tid & 15;

    float acc[4][4];
#pragma unroll
    for (int i = 0; i < 4; ++i)
#pragma unroll
        for (int j = 0; j < 4; ++j) acc[i][j] = 0.f;

    for (int k0 = 0; k0 < Dd; k0 += 16) {
        float4 av = *(const float4*)&A[(m0 + lrow) * Dd + k0 + lkp * 4];
        As[lkp*4+0][lrow] = av.x;
        As[lkp*4+1][lrow] = av.y;
        As[lkp*4+2][lrow] = av.z;
        As[lkp*4+3][lrow] = av.w;
        *(float4*)&Bs[brow][bnp*4] = *(const float4*)&W[(k0 + brow) * N + n0 + bnp*4];
        __syncthreads();
#pragma unroll
        for (int k = 0; k < 16; ++k) {
            float4 a  = *(const float4*)&As[k][tm*4];
            float4 bv = *(const float4*)&Bs[k][tn*4];
            float ar[4] = {a.x, a.y, a.z, a.w};
            float br[4] = {bv.x, bv.y, bv.z, bv.w};
#pragma unroll
            for (int i = 0; i < 4; ++i)
#pragma unroll
                for (int j = 0; j < 4; ++j)
                    acc[i][j] = fmaf(ar[i], br[j], acc[i][j]);
        }
        __syncthreads();
    }

#pragma unroll
    for (int i = 0; i < 4; ++i) {
        const int r  = m0 + tm*4 + i;
        const int bb = r >> 11;           // r / S
        const int ss = r & (Ss - 1);      // r % S
#pragma unroll
        for (int j = 0; j < 4; ++j) {
            const int col = n0 + tn*4 + j;
            const float sg = __fdividef(1.f, 1.f + __expf(-acc[i][j]));
            if (mode == 0) {                   // Q: head = col/16, bit = col%16
                const int h = col >> 4, d = col & 15;
                g_pq[(((bb*Hh + h)*Ss) + ss)*QKBd + d] = sg;
            } else if (mode == 1) {            // K
                const int kv = col >> 4, d = col & 15;
                g_pk[(((bb*KVh + kv)*Ss) + ss)*QKBd + d] = sg;
            } else {                           // V
                const int kv = col >> 5, d = col & 31;
                g_pv[(((bb*KVh + kv)*Ss) + ss)*VBd + d] = sg;
            }
        }
    }
}

// ---------------- Kernel 1b: sk[t] = sum_d pk[t][d] --------------------------
__global__ void sk_kernel()
{
    const int idx = blockIdx.x * 256 + threadIdx.x;     // exact: 64*256 = B*KV*S
    const float4* p = (const float4*)&g_pk[idx * QKBd];
    float4 a = p[0], b = p[1], c = p[2], d = p[3];
    g_sk[idx] = ((a.x + a.y) + (a.z + a.w)) + ((b.x + b.y) + (b.z + b.w))
              + ((c.x + c.y) + (c.z + c.w)) + ((d.x + d.y) + (d.z + d.w));
}

// ---------------- Kernel 1c: bias[d] = sum_j e0[j] * Wo[j][d] ----------------
__global__ void bias_kernel(const float* __restrict__ Wo, const float* __restrict__ e0)
{
    const int d = blockIdx.x * 256 + threadIdx.x;       // exact: 4*256 = 1024
    float s = 0.f;
    for (int j = 0; j < HVB; ++j)
        s = fmaf(e0[j], Wo[j * Dd + d], s);
    g_bias[d] = s;
}

// ---------------- Kernel 2: causal attention ---------------------------------
// logit(s,t) = 2*pq[s].pk[t] - sk[t]; w = exp(logit); vh = sum w*pv / sum w.
// No max-subtraction needed: logits bounded in [-16, 32], fp32-safe.
// Block = 256 threads = 64 queries x 4 sub-threads; key tiles of 64.
#define KSTR 20   // pk tile row stride (16 data + sk + pad) -> conflict-free
#define VSTR 36   // pv tile row stride (32 data + pad)      -> conflict-free

__global__ __launch_bounds__(256) void attn_kernel()
{
    __shared__ float kx[64 * KSTR];
    __shared__ float vx[64 * VSTR];
    const int qt  = (Ss/64 - 1) - blockIdx.x;   // reversed: heavy tiles first
    const int h   = blockIdx.y;
    const int bb  = blockIdx.z;
    const int kvh = h >> 2;                     // h / NREP
    const int tid = threadIdx.x;
    const int ql  = tid >> 2;                   // local query 0..63
    const int sub = tid & 3;                    // key-lane within query group
    const int q0  = qt * 64;
    const int qg  = q0 + ql;

    const float* __restrict__ pqr = &g_pq[((bb*Hh + h)*Ss + qg) * QKBd];
    const float4 qa = *(const float4*)&pqr[0];
    const float4 qb = *(const float4*)&pqr[4];
    const float4 qc = *(const float4*)&pqr[8];
    const float4 qd = *(const float4*)&pqr[12];

    const float* __restrict__ pkb = &g_pk[(bb*KVh + kvh) * Ss * QKBd];
    const float* __restrict__ skb = &g_sk[(bb*KVh + kvh) * Ss];
    const float* __restrict__ pvb = &g_pv[(bb*KVh + kvh) * Ss * VBd];

    float l = 0.f;
    float acc[VBd];
#pragma unroll
    for (int j = 0; j < VBd; ++j) acc[j] = 0.f;

    const int row  = tid >> 2;   // tile-fill row 0..63
    const int part = tid & 3;

    for (int kt = 0; kt <= qt; ++kt) {
        const int t0 = kt * 64;
        *(float4*)&kx[row*KSTR + part*4] =
            *(const float4*)&pkb[(t0 + row)*QKBd + part*4];
        if (tid < 64) kx[tid*KSTR + 16] = skb[t0 + tid];
        *(float4*)&vx[row*VSTR + part*8] =
            *(const float4*)&pvb[(t0 + row)*VBd + part*8];
        *(float4*)&vx[row*VSTR + part*8 + 4] =
            *(const float4*)&pvb[(t0 + row)*VBd + part*8 + 4];
        __syncthreads();

        const bool bnd = (kt == qt);   // only the diagonal tile needs the mask
#pragma unroll 8
        for (int i = 0; i < 16; ++i) {
            const int kk = sub + i*4;
            const float* kr = &kx[kk * KSTR];
            const float4 k0 = *(const float4*)&kr[0];
            const float4 k1 = *(const float4*)&kr[4];
            const float4 k2 = *(const float4*)&kr[8];
            const float4 k3 = *(const float4*)&kr[12];
            float s0 = fmaf(k0.x,qa.x, fmaf(k0.y,qa.y, fmaf(k0.z,qa.z, k0.w*qa.w)));
            float s1 = fmaf(k1.x,qb.x, fmaf(k1.y,qb.y, fmaf(k1.z,qb.z, k1.w*qb.w)));
            float s2 = fmaf(k2.x,qc.x, fmaf(k2.y,qc.y, fmaf(k2.z,qc.z, k2.w*qc.w)));
            float s3 = fmaf(k3.x,qd.x, fmaf(k3.y,qd.y, fmaf(k3.z,qd.z, k3.w*qd.w)));
            const float dot = (s0 + s1) + (s2 + s3);
            const float x = fmaf(dot, 2.f, -kr[16]);
            float w = __expf(x);
            if (bnd && kk > ql) w = 0.f;      // causal
            l += w;
            const float* vr = &vx[kk * VSTR];
#pragma unroll
            for (int v4 = 0; v4 < 8; ++v4) {
                const float4 vv = *(const float4*)&vr[v4*4];
                acc[v4*4+0] = fmaf(w, vv.x, acc[v4*4+0]);
                acc[v4*4+1] = fmaf(w, vv.y, acc[v4*4+1]);
                acc[v4*4+2] = fmaf(w, vv.z, acc[v4*4+2]);
                acc[v4*4+3] = fmaf(w, vv.w, acc[v4*4+3]);
            }
        }
        __syncthreads();
    }

    // reduce over the 4 sub-threads of each query (lanes 4g..4g+3)
#pragma unroll
    for (int off = 1; off < 4; off <<= 1) {
        l += __shfl_xor_sync(0xffffffffu, l, off);
#pragma unroll
        for (int j = 0; j < VBd; ++j)
            acc[j] += __shfl_xor_sync(0xffffffffu, acc[j], off);
    }

    if (sub == 0) {
        const float invl = 1.f / l;
        float* orow = &g_vh[(bb*Ss + qg)*HVB + h*VBd];
#pragma unroll
        for (int v4 = 0; v4 < 8; ++v4) {
            float4 o;
            o.x = acc[v4*4+0] * invl;
            o.y = acc[v4*4+1] * invl;
            o.z = acc[v4*4+2] * invl;
            o.w = acc[v4*4+3] * invl;
            *(float4*)&orow[v4*4] = o;
        }
    }
}

// ---------------- Kernel 3: out = ((e1-e0) o vh) @ Wo + bias -----------------
__global__ __launch_bounds__(256) void out_kernel(
    const float* __restrict__ Wo, const float* __restrict__ e0,
    const float* __restrict__ e1, float* __restrict__ out)
{
    __shared__ float As[16][68];
    __shared__ float Bs[16][68];
    __shared__ float sc[HVB];
    const int m0 = blockIdx.x * 64;
    const int n0 = blockIdx.y * 64;
    const int tid = threadIdx.x;
    const int tm = tid >> 4, tn = tid & 15;
    const int lrow = tid >> 2, lkp = tid & 3;
    const int brow = tid >> 4, bnp = tid & 15;

    sc[tid]       = e1[tid]       - e0[tid];
    sc[tid + 256] = e1[tid + 256] - e0[tid + 256];
    __syncthreads();

    float acc[4][4];
#pragma unroll
    for (int i = 0; i < 4; ++i)
#pragma unroll
        for (int j = 0; j < 4; ++j) acc[i][j] = 0.f;

    for (int k0 = 0; k0 < HVB; k0 += 16) {
        float4 av = *(const float4*)&g_vh[(m0 + lrow)*HVB + k0 + lkp*4];
        As[lkp*4+0][lrow] = av.x * sc[k0 + lkp*4 + 0];
        As[lkp*4+1][lrow] = av.y * sc[k0 + lkp*4 + 1];
        As[lkp*4+2][lrow] = av.z * sc[k0 + lkp*4 + 2];
        As[lkp*4+3][lrow] = av.w * sc[k0 + lkp*4 + 3];
        *(float4*)&Bs[brow][bnp*4] = *(const float4*)&Wo[(k0 + brow)*Dd + n0 + bnp*4];
        __syncthreads();
#pragma unroll
        for (int k = 0; k < 16; ++k) {
            float4 a  = *(const float4*)&As[k][tm*4];
            float4 bv = *(const float4*)&Bs[k][tn*4];
            float ar[4] = {a.x, a.y, a.z, a.w};
            float br[4] = {bv.x, bv.y, bv.z, bv.w};
#pragma unroll
            for (int i = 0; i < 4; ++i)
#pragma unroll
                for (int j = 0; j < 4; ++j)
                    acc[i][j] = fmaf(ar[i], br[j], acc[i][j]);
        }
        __syncthreads();
    }

#pragma unroll
    for (int i = 0; i < 4; ++i) {
        const int r = m0 + tm*4 + i;
#pragma unroll
        for (int j = 0; j < 4; ++j) {
            const int col = n0 + tn*4 + j;
            out[r*Dd + col] = acc[i][j] + g_bias[col];
        }
    }
}

// ---------------- launch -----------------------------------------------------
extern "C" void kernel_launch(void* const* d_in, const int* in_sizes, int n_in,
                              void* d_out, int out_size)
{
    const float* hs = (const float*)d_in[0];
    const float* Wq = (const float*)d_in[1];
    const float* Wk = (const float*)d_in[2];
    const float* Wv = (const float*)d_in[3];
    const float* Wo = (const float*)d_in[4];
    const float* e0 = (const float*)d_in[5];
    const float* e1 = (const float*)d_in[6];
    float* out = (float*)d_out;

    dim3 blk(256);
    proj_kernel<<<dim3(MROWS/64, 4), blk>>>(hs, Wq, Hh*QKBd, 0);   // Q: N=256
    proj_kernel<<<dim3(MROWS/64, 1), blk>>>(hs, Wk, KVh*QKBd, 1);  // K: N=64
    proj_kernel<<<dim3(MROWS/64, 2), blk>>>(hs, Wv, KVh*VBd, 2);   // V: N=128
    sk_kernel<<<(Bb*KVh*Ss)/256, 256>>>();
    bias_kernel<<<Dd/256, 256>>>(Wo, e0);
    attn_kernel<<<dim3(Ss/64, Hh, Bb), blk>>>();
    out_kernel<<<dim3(MROWS/64, Dd/64), blk>>>(Wo, e0, e1, out);
}